// round 1
// baseline (speedup 1.0000x reference)
#include <cuda_runtime.h>
#include <cuda_bf16.h>

// Fast Walsh-Hadamard transform, 16384 rows x 1024 fp32.
// y[row] = FWHT(x[row]) / 32, emitted as interleaved (real, 0) pairs.
//
// Layout per row: 128 threads, 8 elements/thread.
//   stage strides 1,2,4      -> register butterflies
//   stage strides 8..128     -> warp shuffle butterflies (lane xor 1..16)
//   stage strides 256,512    -> one smem transpose, then register butterflies
// Only one __syncthreads per row; smem traffic is 8KB/row instead of 80KB.

#define DIMN 1024
#define TPR  128          // threads per row
#define RPB  2            // rows per block -> 256 threads/block

__device__ __forceinline__ void bf(float &x, float &y) {
    float s = x + y;
    y = x - y;
    x = s;
}

__global__ void __launch_bounds__(TPR * RPB, 8)
fwht_kernel(const float4* __restrict__ xin, float4* __restrict__ yout, int nrows)
{
    __shared__ float sm[RPB][DIMN];
    const int t   = threadIdx.x & (TPR - 1);   // thread within row
    const int rl  = threadIdx.x / TPR;         // local row in block
    const int row = blockIdx.x * RPB + rl;
    const bool active = (row < nrows);

    float v[8];
    if (active) {
        const float4* base = xin + (size_t)row * (DIMN / 4);
        float4 p0 = base[2 * t];
        float4 p1 = base[2 * t + 1];
        v[0] = p0.x; v[1] = p0.y; v[2] = p0.z; v[3] = p0.w;
        v[4] = p1.x; v[5] = p1.y; v[6] = p1.z; v[7] = p1.w;
    } else {
        #pragma unroll
        for (int j = 0; j < 8; j++) v[j] = 0.0f;
    }

    // ---- strides 1, 2, 4 (within the 8 registers; element idx = 8t + j) ----
    bf(v[0], v[1]); bf(v[2], v[3]); bf(v[4], v[5]); bf(v[6], v[7]);
    bf(v[0], v[2]); bf(v[1], v[3]); bf(v[4], v[6]); bf(v[5], v[7]);
    bf(v[0], v[4]); bf(v[1], v[5]); bf(v[2], v[6]); bf(v[3], v[7]);

    // ---- strides 8,16,32,64,128 via shfl.xor (partner thread t ^ d) ----
    #pragma unroll
    for (int d = 1; d <= 16; d <<= 1) {
        const bool upper = (t & d) != 0;
        #pragma unroll
        for (int j = 0; j < 8; j++) {
            float o = __shfl_xor_sync(0xffffffffu, v[j], d);
            v[j] = upper ? (o - v[j]) : (v[j] + o);
        }
    }

    // ---- smem transpose: re-gather so strides 256/512 are register-local ----
    float4* smw = reinterpret_cast<float4*>(&sm[rl][8 * t]);
    smw[0] = make_float4(v[0], v[1], v[2], v[3]);
    smw[1] = make_float4(v[4], v[5], v[6], v[7]);
    __syncthreads();

    // thread t now takes elements {2t, 2t+1} + 256k for k=0..3
    const float2* smr = reinterpret_cast<const float2*>(sm[rl]);
    float a[4], b[4];
    #pragma unroll
    for (int k = 0; k < 4; k++) {
        float2 p = smr[t + 128 * k];
        a[k] = p.x;      // element 2t   + 256k
        b[k] = p.y;      // element 2t+1 + 256k
    }

    // ---- strides 256, 512 (now butterflies over k) ----
    bf(a[0], a[1]); bf(a[2], a[3]); bf(b[0], b[1]); bf(b[2], b[3]);
    bf(a[0], a[2]); bf(a[1], a[3]); bf(b[0], b[2]); bf(b[1], b[3]);

    // ---- scaled store as interleaved (real, 0) pairs; coalesced float4 ----
    if (active) {
        const float s = 0.03125f;  // 1/sqrt(1024)
        float4* ob = yout + (size_t)row * (2 * DIMN / 4);
        #pragma unroll
        for (int k = 0; k < 4; k++) {
            // covers out floats [4t + 512k, 4t + 512k + 3]
            ob[t + 128 * k] = make_float4(a[k] * s, 0.0f, b[k] * s, 0.0f);
        }
    }
}

extern "C" void kernel_launch(void* const* d_in, const int* in_sizes, int n_in,
                              void* d_out, int out_size)
{
    const float* x = (const float*)d_in[0];   // [B, S, 1024] fp32
    // d_in[1] is H; unused — the transform is computed directly.
    float* out = (float*)d_out;               // [B, S, 1024, 2] fp32

    const int nrows = in_sizes[0] / DIMN;     // 16384
    const int grid  = (nrows + RPB - 1) / RPB;

    fwht_kernel<<<grid, TPR * RPB>>>((const float4*)x, (float4*)out, nrows);
}